// round 7
// baseline (speedup 1.0000x reference)
#include <cuda_runtime.h>
#include <cstdint>

#define BATCH 32
#define CH    256
#define HH    56
#define WW    56
#define HW    3136
#define KK2   2304      // CH*9
#define MEXP  8

#define BM 128          // o per CTA
#define BN 64           // pixels per CTA (49*64 = 3136 exact)
#define BK 32           // k per chunk
#define NCHUNK (KK2 / BK)   // 72

// smem rows: 32 tf32 = 128B data + 16B pad = 144B (9*16B -> conflict-free ldmatrix)
#define ROWB   144
#define ATILE  (128 * ROWB)     // 18432
#define BTILE  (64 * ROWB)      // 9216
#define STAGE  (ATILE + BTILE)  // 27648
#define NSTAGE 3
#define SMEM_BYTES (NSTAGE * STAGE)   // 82944

// Scratch
__device__ float    g_gap[BATCH * CH];
__device__ float    g_alpha[BATCH * MEXP];
__device__ float    g_biasc[BATCH * CH];
__device__ uint32_t g_wt[(size_t)BATCH * CH * KK2];   // combined weights, tf32 [b][o][k]
__device__ uint32_t g_xt[(size_t)BATCH * CH * HW];    // x as tf32

// ---------------- helpers ----------------
__device__ __forceinline__ uint32_t smem_u32(const void* p) {
    uint32_t a;
    asm("{ .reg .u64 t; cvta.to.shared.u64 t, %1; cvt.u32.u64 %0, t; }" : "=r"(a) : "l"(p));
    return a;
}
__device__ __forceinline__ uint32_t f2tf32(float f) {
    uint32_t r; asm("cvt.rna.tf32.f32 %0, %1;" : "=r"(r) : "f"(f)); return r;
}
__device__ __forceinline__ void ldsm4(uint32_t& r0, uint32_t& r1, uint32_t& r2, uint32_t& r3,
                                      uint32_t addr) {
    asm volatile("ldmatrix.sync.aligned.m8n8.x4.shared.b16 {%0,%1,%2,%3}, [%4];"
                 : "=r"(r0), "=r"(r1), "=r"(r2), "=r"(r3) : "r"(addr));
}
__device__ __forceinline__ void mma_tf32(float* c, const uint32_t* a, uint32_t b0, uint32_t b1) {
    asm volatile(
        "mma.sync.aligned.m16n8k8.row.col.f32.tf32.tf32.f32 "
        "{%0,%1,%2,%3}, {%4,%5,%6,%7}, {%8,%9}, {%0,%1,%2,%3};"
        : "+f"(c[0]), "+f"(c[1]), "+f"(c[2]), "+f"(c[3])
        : "r"(a[0]), "r"(a[1]), "r"(a[2]), "r"(a[3]), "r"(b0), "r"(b1));
}
__device__ __forceinline__ void cpasync16(uint32_t dst, const void* src) {
    asm volatile("cp.async.cg.shared.global [%0], [%1], 16;" :: "r"(dst), "l"(src) : "memory");
}
__device__ __forceinline__ void cpasync4z(uint32_t dst, const void* src, uint32_t srcsz) {
    asm volatile("cp.async.ca.shared.global [%0], [%1], 4, %2;"
                 :: "r"(dst), "l"(src), "r"(srcsz) : "memory");
}

// ---------------------------------------------------------------------------
// 1) Global average pool
// ---------------------------------------------------------------------------
__global__ void gap_kernel(const float* __restrict__ x) {
    int bc = blockIdx.x;
    const float* p = x + (size_t)bc * HW;
    float s = 0.f;
    for (int i = threadIdx.x; i < HW; i += 128) s += p[i];
    __shared__ float sm[4];
    #pragma unroll
    for (int off = 16; off; off >>= 1) s += __shfl_down_sync(0xffffffffu, s, off);
    if ((threadIdx.x & 31) == 0) sm[threadIdx.x >> 5] = s;
    __syncthreads();
    if (threadIdx.x == 0)
        g_gap[bc] = (sm[0] + sm[1] + sm[2] + sm[3]) * (1.f / (float)HW);
}

// ---------------------------------------------------------------------------
// 2) Gate softmax + combined bias
// ---------------------------------------------------------------------------
__global__ void gate_kernel(const float* __restrict__ gate_w,
                            const float* __restrict__ gate_b,
                            const float* __restrict__ bias) {
    __shared__ float lg[BATCH][MEXP];
    __shared__ float al[BATCH][MEXP];
    int t = threadIdx.x;
    int b = t >> 3, m = t & 7;
    float acc = gate_b[m];
    const float* gp = &g_gap[b * CH];
    const float* gw = &gate_w[m * CH];
    for (int i = 0; i < CH; i++) acc += gp[i] * gw[i];
    lg[b][m] = acc;
    __syncthreads();
    if (t < BATCH) {
        float mx = lg[t][0];
        #pragma unroll
        for (int j = 1; j < MEXP; j++) mx = fmaxf(mx, lg[t][j]);
        float e[MEXP], s = 0.f;
        #pragma unroll
        for (int j = 0; j < MEXP; j++) { e[j] = expf(lg[t][j] - mx); s += e[j]; }
        float inv = 1.f / s;
        #pragma unroll
        for (int j = 0; j < MEXP; j++) { al[t][j] = e[j] * inv; g_alpha[t * MEXP + j] = e[j] * inv; }
    }
    __syncthreads();
    for (int b2 = 0; b2 < BATCH; b2++) {
        float s = 0.f;
        #pragma unroll
        for (int j = 0; j < MEXP; j++) s += al[b2][j] * bias[j * CH + t];
        g_biasc[b2 * CH + t] = s;
    }
}

// ---------------------------------------------------------------------------
// 3) Combine experts -> tf32
// ---------------------------------------------------------------------------
__global__ void combine_kernel(const float* __restrict__ weight) {
    int b = blockIdx.y;
    size_t i4 = (size_t)blockIdx.x * 256 + threadIdx.x;
    float a[MEXP];
    #pragma unroll
    for (int m = 0; m < MEXP; m++) a[m] = g_alpha[b * MEXP + m];
    float4 acc = make_float4(0.f, 0.f, 0.f, 0.f);
    #pragma unroll
    for (int m = 0; m < MEXP; m++) {
        const float4 v = ((const float4*)(weight + (size_t)m * CH * KK2))[i4];
        acc.x += a[m] * v.x; acc.y += a[m] * v.y;
        acc.z += a[m] * v.z; acc.w += a[m] * v.w;
    }
    uint4 o;
    o.x = f2tf32(acc.x); o.y = f2tf32(acc.y);
    o.z = f2tf32(acc.z); o.w = f2tf32(acc.w);
    ((uint4*)(g_wt + (size_t)b * CH * KK2))[i4] = o;
}

// ---------------------------------------------------------------------------
// 3b) x -> tf32
// ---------------------------------------------------------------------------
__global__ void xsplit_kernel(const float* __restrict__ x) {
    size_t i4 = (size_t)blockIdx.x * 256 + threadIdx.x;
    float4 v = ((const float4*)x)[i4];
    uint4 o;
    o.x = f2tf32(v.x); o.y = f2tf32(v.y);
    o.z = f2tf32(v.z); o.w = f2tf32(v.w);
    ((uint4*)g_xt)[i4] = o;
}

// ---------------------------------------------------------------------------
// 4) Conv GEMM: tf32 mma.sync m16n8k8, single pass, all-cp.async producers.
//    Tiles 128(o) x 64(pix) x 32(k); grid (49, 2, 32); 8 warps, warp = m16 x n64.
//    3-stage cp.async pipeline, 2 CTAs/SM.
// ---------------------------------------------------------------------------
__global__ void __launch_bounds__(256, 2)
conv_mma_kernel(float* __restrict__ out) {
    extern __shared__ char smem[];
    const uint32_t sbase = smem_u32(smem);
    const int tid  = threadIdx.x;
    const int wid  = tid >> 5;
    const int lane = tid & 31;

    const int b  = blockIdx.z;
    const int o0 = blockIdx.y * BM;
    const int p0 = blockIdx.x * BN;

    // A producer: thread -> (o-row ar, 64B half seg): 4 x cp.async.16
    const int ar  = tid >> 1;
    const int seg = tid & 1;
    const uint32_t* wRow = g_wt + ((size_t)(b * CH) + o0 + ar) * KK2 + seg * 16;
    const uint32_t aDst = (uint32_t)ar * ROWB + seg * 64;

    // B producer: warp owns k = kc + wid*4..+3 ; pixel rows lane + 32j
    int hj[2], wj[2];
    #pragma unroll
    for (int j = 0; j < 2; j++) {
        int p = p0 + lane + 32 * j;
        hj[j] = p / WW;
        wj[j] = p - hj[j] * WW;
    }
    const uint32_t* xb = g_xt + (size_t)b * CH * HW;

    // consumer ldmatrix addresses
    const uint32_t aLd = sbase + (uint32_t)(wid * 16 + (lane & 15)) * ROWB + (lane >> 4) * 16;
    const uint32_t bLd = sbase + ATILE + (uint32_t)(lane & 7) * ROWB + (lane >> 3) * 16;

    float acc[8][4];
    #pragma unroll
    for (int j = 0; j < 8; j++)
        #pragma unroll
        for (int q = 0; q < 4; q++) acc[j][q] = 0.f;

    auto issueStage = [&](int chunk, int s) {
        const uint32_t stg = sbase + s * STAGE;
        // A tile
        const uint32_t* srcA = wRow + chunk * BK;
        const uint32_t dA = stg + aDst;
        cpasync16(dA,      srcA);
        cpasync16(dA + 16, srcA + 4);
        cpasync16(dA + 32, srcA + 8);
        cpasync16(dA + 48, srcA + 12);
        // B tile (implicit im2col gather, 4B with zero-fill)
        const int kb = chunk * BK + wid * 4;
        #pragma unroll
        for (int kk = 0; kk < 4; kk++) {
            int k  = kb + kk;
            int c  = k / 9;
            int r  = k - c * 9;
            int r3 = r / 3;
            int dh = r3 - 1;
            int dw = r - r3 * 3 - 1;
            const uint32_t* xc = xb + (size_t)c * HW;
            #pragma unroll
            for (int j = 0; j < 2; j++) {
                int ih = hj[j] + dh;
                int iw = wj[j] + dw;
                bool ok = ((unsigned)ih < HH) && ((unsigned)iw < WW);
                const uint32_t* src = ok ? (xc + ih * WW + iw) : xc;
                uint32_t dst = stg + ATILE + (uint32_t)(lane + 32 * j) * ROWB
                             + (uint32_t)(wid * 4 + kk) * 4;
                cpasync4z(dst, src, ok ? 4u : 0u);
            }
        }
        asm volatile("cp.async.commit_group;" ::: "memory");
    };

    // ---- prologue: stages 0,1 ----
    issueStage(0, 0);
    issueStage(1, 1);

    int sIdx = 0;
    for (int c0 = 0; c0 < NCHUNK; c0++) {
        if (c0 + 2 < NCHUNK) {
            issueStage(c0 + 2, (sIdx + 2) % NSTAGE);
            asm volatile("cp.async.wait_group 2;" ::: "memory");
        } else if (c0 + 2 == NCHUNK) {
            asm volatile("cp.async.wait_group 1;" ::: "memory");
        } else {
            asm volatile("cp.async.wait_group 0;" ::: "memory");
        }
        __syncthreads();

        const uint32_t sA = aLd + sIdx * STAGE;
        const uint32_t sB = bLd + sIdx * STAGE;

        #pragma unroll
        for (int t = 0; t < 2; t++) {
            uint32_t a0[4], a1[4], bb[8][4];
            ldsm4(a0[0], a0[1], a0[2], a0[3], sA + (2 * t) * 32);
            ldsm4(a1[0], a1[1], a1[2], a1[3], sA + (2 * t + 1) * 32);
            #pragma unroll
            for (int nb = 0; nb < 8; nb++)
                ldsm4(bb[nb][0], bb[nb][1], bb[nb][2], bb[nb][3],
                      sB + nb * (8 * ROWB) + t * 64);
            #pragma unroll
            for (int nb = 0; nb < 8; nb++)
                mma_tf32(acc[nb], a0, bb[nb][0], bb[nb][1]);
            #pragma unroll
            for (int nb = 0; nb < 8; nb++)
                mma_tf32(acc[nb], a1, bb[nb][2], bb[nb][3]);
        }
        __syncthreads();
        sIdx = (sIdx + 1) % NSTAGE;
    }

    // ---- epilogue ----
    {
        int r0 = o0 + wid * 16 + (lane >> 2);
        float bi0 = g_biasc[b * CH + r0];
        float bi1 = g_biasc[b * CH + r0 + 8];
        float* out0 = out + ((size_t)b * CH + r0) * HW;
        float* out1 = out0 + 8 * HW;
        #pragma unroll
        for (int nb = 0; nb < 8; nb++) {
            int p = p0 + nb * 8 + (lane & 3) * 2;
            *(float2*)(out0 + p) = make_float2(acc[nb][0] + bi0, acc[nb][1] + bi0);
            *(float2*)(out1 + p) = make_float2(acc[nb][2] + bi1, acc[nb][3] + bi1);
        }
    }
}

// ---------------------------------------------------------------------------
extern "C" void kernel_launch(void* const* d_in, const int* in_sizes, int n_in,
                              void* d_out, int out_size) {
    const float* x      = (const float*)d_in[0];
    const float* weight = (const float*)d_in[1];
    const float* bias   = (const float*)d_in[2];
    const float* gate_w = (const float*)d_in[3];
    const float* gate_b = (const float*)d_in[4];
    float* out = (float*)d_out;

    cudaFuncSetAttribute(conv_mma_kernel,
                         cudaFuncAttributeMaxDynamicSharedMemorySize, SMEM_BYTES);

    gap_kernel<<<BATCH * CH, 128>>>(x);
    gate_kernel<<<1, 256>>>(gate_w, gate_b, bias);
    combine_kernel<<<dim3(CH * KK2 / 4 / 256, BATCH), 256>>>(weight);
    xsplit_kernel<<<(int)((size_t)BATCH * CH * HW / 4 / 256), 256>>>(x);
    conv_mma_kernel<<<dim3(HW / BN, CH / BM, BATCH), 256, SMEM_BYTES>>>(out);
}

// round 10
// speedup vs baseline: 1.1758x; 1.1758x over previous
#include <cuda_runtime.h>
#include <cstdint>

#define BATCH 32
#define CH    256
#define HH    56
#define WW    56
#define HW    3136
#define KK2   2304      // CH*9
#define MEXP  8

#define BM 128          // o per CTA
#define BN 64           // pixels per CTA (49*64 = 3136 exact)
#define BK 32           // k per chunk
#define NCHUNK (KK2 / BK)   // 72

// swizzled smem: row stride 128B, 16B-group index XOR (row&7) -> conflict-free
#define ATILE  (128 * 128)      // 16384
#define BTILE  (64 * 128)       // 8192
#define STAGE  (ATILE + BTILE)  // 24576
#define NSTAGE 3
#define SMEM_BYTES (NSTAGE * STAGE)   // 73728

// Scratch
__device__ float    g_gap[BATCH * CH];
__device__ float    g_alpha[BATCH * MEXP];
__device__ float    g_biasc[BATCH * CH];
__device__ uint32_t g_wt[(size_t)BATCH * CH * KK2];   // combined weights, tf32 [b][o][k]
__device__ uint32_t g_xt[(size_t)BATCH * CH * HW];    // x as tf32

// conv offset per kernel-position r: (r/3-1)*56 + (r%3-1)
__constant__ int c_doff[9] = { -57, -56, -55, -1, 0, 1, 55, 56, 57 };

// ---------------- helpers ----------------
__device__ __forceinline__ uint32_t smem_u32(const void* p) {
    uint32_t a;
    asm("{ .reg .u64 t; cvta.to.shared.u64 t, %1; cvt.u32.u64 %0, t; }" : "=r"(a) : "l"(p));
    return a;
}
__device__ __forceinline__ uint32_t f2tf32(float f) {
    uint32_t r; asm("cvt.rna.tf32.f32 %0, %1;" : "=r"(r) : "f"(f)); return r;
}
__device__ __forceinline__ void ldsm4(uint32_t& r0, uint32_t& r1, uint32_t& r2, uint32_t& r3,
                                      uint32_t addr) {
    asm volatile("ldmatrix.sync.aligned.m8n8.x4.shared.b16 {%0,%1,%2,%3}, [%4];"
                 : "=r"(r0), "=r"(r1), "=r"(r2), "=r"(r3) : "r"(addr));
}
__device__ __forceinline__ void mma_tf32(float* c, const uint32_t* a, uint32_t b0, uint32_t b1) {
    asm volatile(
        "mma.sync.aligned.m16n8k8.row.col.f32.tf32.tf32.f32 "
        "{%0,%1,%2,%3}, {%4,%5,%6,%7}, {%8,%9}, {%0,%1,%2,%3};"
        : "+f"(c[0]), "+f"(c[1]), "+f"(c[2]), "+f"(c[3])
        : "r"(a[0]), "r"(a[1]), "r"(a[2]), "r"(a[3]), "r"(b0), "r"(b1));
}
__device__ __forceinline__ void cpasync16(uint32_t dst, const void* src) {
    asm volatile("cp.async.cg.shared.global [%0], [%1], 16;" :: "r"(dst), "l"(src) : "memory");
}
__device__ __forceinline__ void cpasync4z(uint32_t dst, const void* src, uint32_t srcsz) {
    asm volatile("cp.async.ca.shared.global [%0], [%1], 4, %2;"
                 :: "r"(dst), "l"(src), "r"(srcsz) : "memory");
}

// ---------------------------------------------------------------------------
// 1) Global average pool
// ---------------------------------------------------------------------------
__global__ void gap_kernel(const float* __restrict__ x) {
    int bc = blockIdx.x;
    const float* p = x + (size_t)bc * HW;
    float s = 0.f;
    for (int i = threadIdx.x; i < HW; i += 128) s += p[i];
    __shared__ float sm[4];
    #pragma unroll
    for (int off = 16; off; off >>= 1) s += __shfl_down_sync(0xffffffffu, s, off);
    if ((threadIdx.x & 31) == 0) sm[threadIdx.x >> 5] = s;
    __syncthreads();
    if (threadIdx.x == 0)
        g_gap[bc] = (sm[0] + sm[1] + sm[2] + sm[3]) * (1.f / (float)HW);
}

// ---------------------------------------------------------------------------
// 2) Gate softmax + combined bias
// ---------------------------------------------------------------------------
__global__ void gate_kernel(const float* __restrict__ gate_w,
                            const float* __restrict__ gate_b,
                            const float* __restrict__ bias) {
    __shared__ float lg[BATCH][MEXP];
    __shared__ float al[BATCH][MEXP];
    int t = threadIdx.x;
    int b = t >> 3, m = t & 7;
    float acc = gate_b[m];
    const float* gp = &g_gap[b * CH];
    const float* gw = &gate_w[m * CH];
    for (int i = 0; i < CH; i++) acc += gp[i] * gw[i];
    lg[b][m] = acc;
    __syncthreads();
    if (t < BATCH) {
        float mx = lg[t][0];
        #pragma unroll
        for (int j = 1; j < MEXP; j++) mx = fmaxf(mx, lg[t][j]);
        float e[MEXP], s = 0.f;
        #pragma unroll
        for (int j = 0; j < MEXP; j++) { e[j] = expf(lg[t][j] - mx); s += e[j]; }
        float inv = 1.f / s;
        #pragma unroll
        for (int j = 0; j < MEXP; j++) { al[t][j] = e[j] * inv; g_alpha[t * MEXP + j] = e[j] * inv; }
    }
    __syncthreads();
    for (int b2 = 0; b2 < BATCH; b2++) {
        float s = 0.f;
        #pragma unroll
        for (int j = 0; j < MEXP; j++) s += al[b2][j] * bias[j * CH + t];
        g_biasc[b2 * CH + t] = s;
    }
}

// ---------------------------------------------------------------------------
// 3) Combine experts -> tf32
// ---------------------------------------------------------------------------
__global__ void combine_kernel(const float* __restrict__ weight) {
    int b = blockIdx.y;
    size_t i4 = (size_t)blockIdx.x * 256 + threadIdx.x;
    float a[MEXP];
    #pragma unroll
    for (int m = 0; m < MEXP; m++) a[m] = g_alpha[b * MEXP + m];
    float4 acc = make_float4(0.f, 0.f, 0.f, 0.f);
    #pragma unroll
    for (int m = 0; m < MEXP; m++) {
        const float4 v = ((const float4*)(weight + (size_t)m * CH * KK2))[i4];
        acc.x += a[m] * v.x; acc.y += a[m] * v.y;
        acc.z += a[m] * v.z; acc.w += a[m] * v.w;
    }
    uint4 o;
    o.x = f2tf32(acc.x); o.y = f2tf32(acc.y);
    o.z = f2tf32(acc.z); o.w = f2tf32(acc.w);
    ((uint4*)(g_wt + (size_t)b * CH * KK2))[i4] = o;
}

// ---------------------------------------------------------------------------
// 3b) x -> tf32
// ---------------------------------------------------------------------------
__global__ void xsplit_kernel(const float* __restrict__ x) {
    size_t i4 = (size_t)blockIdx.x * 256 + threadIdx.x;
    float4 v = ((const float4*)x)[i4];
    uint4 o;
    o.x = f2tf32(v.x); o.y = f2tf32(v.y);
    o.z = f2tf32(v.z); o.w = f2tf32(v.w);
    ((uint4*)g_xt)[i4] = o;
}

// ---------------------------------------------------------------------------
// 4) Conv GEMM: tf32 mma.sync m16n8k8, swizzled smem, incremental im2col.
//    Tiles 128(o) x 64(pix) x 32(k); grid (49, 2, 32); 8 warps, warp m16 x n64.
//    3-stage cp.async pipeline, 3 CTAs/SM (24 warps).
// ---------------------------------------------------------------------------
__global__ void __launch_bounds__(256, 3)
conv_mma_kernel(float* __restrict__ out) {
    extern __shared__ char smem[];
    const uint32_t sbase = smem_u32(smem);
    const int tid  = threadIdx.x;
    const int wid  = tid >> 5;
    const int lane = tid & 31;

    const int b  = blockIdx.z;
    const int o0 = blockIdx.y * BM;
    const int p0 = blockIdx.x * BN;

    // ---- A producer: thread -> (o-row ar, half seg): 4 x cp.async.16, swizzled
    const int ar  = tid >> 1;
    const int seg = tid & 1;
    const uint32_t* wRow = g_wt + ((size_t)(b * CH) + o0 + ar) * KK2 + seg * 16;
    const uint32_t ars = (uint32_t)(ar & 7);
    uint32_t aDstG[4];
    #pragma unroll
    for (int q = 0; q < 4; q++)
        aDstG[q] = (uint32_t)ar * 128 + (((uint32_t)(seg * 4 + q) ^ ars) << 4);

    // ---- B producer: warp owns k = kc + wid*4..+3 ; pixel rows lane + 32j
    int pj[2];
    uint32_t vmask[2];
    #pragma unroll
    for (int j = 0; j < 2; j++) {
        int p = p0 + lane + 32 * j;
        pj[j] = p;
        int hjv = p / WW, wjv = p - (p / WW) * WW;
        uint32_t m = 0;
        #pragma unroll
        for (int r = 0; r < 9; r++) {
            int ih = hjv + r / 3 - 1;
            int iw = wjv + r % 3 - 1;
            if ((unsigned)ih < HH && (unsigned)iw < WW) m |= (1u << r);
        }
        vmask[j] = m;
    }
    // incremental (r, channel-offset) per kk
    int rst[4], coff[4];
    #pragma unroll
    for (int kk = 0; kk < 4; kk++) {
        int k0 = wid * 4 + kk;
        int c0 = k0 / 9;
        rst[kk]  = k0 - 9 * c0;
        coff[kk] = c0 * HW;
    }
    const uint32_t* xb = g_xt + (size_t)b * CH * HW;
    // swizzled B dst: prow*128 + ((wid ^ (prow&7))<<4) + kk*4
    uint32_t bDst[2];
    #pragma unroll
    for (int j = 0; j < 2; j++) {
        uint32_t prow = (uint32_t)(lane + 32 * j);
        bDst[j] = ATILE + prow * 128 + ((uint32_t)(wid ^ (prow & 7)) << 4);
    }

    // ---- consumer addresses
    const uint32_t ls  = (uint32_t)(lane & 7);                 // swizzle key
    const uint32_t aRowBase = (uint32_t)(wid * 16 + (lane & 15)) * 128;
    const uint32_t aHi = (uint32_t)(lane >> 4);                // 0/1
    const uint32_t bHi = (uint32_t)(lane >> 3);                // 0..3

    float acc[8][4];
    #pragma unroll
    for (int j = 0; j < 8; j++)
        #pragma unroll
        for (int q = 0; q < 4; q++) acc[j][q] = 0.f;

    auto issueStage = [&](int chunk, int s) {
        const uint32_t stg = sbase + s * STAGE;
        // A
        const uint32_t* srcA = wRow + chunk * BK;
        #pragma unroll
        for (int q = 0; q < 4; q++) cpasync16(stg + aDstG[q], srcA + q * 4);
        // B gather
        #pragma unroll
        for (int kk = 0; kk < 4; kk++) {
            int rr = rst[kk];
            int base = coff[kk] + c_doff[rr];
            #pragma unroll
            for (int j = 0; j < 2; j++) {
                uint32_t ok = (vmask[j] >> rr) & 1u;
                const uint32_t* src = ok ? (xb + base + pj[j]) : xb;
                cpasync4z(stg + bDst[j] + kk * 4, src, ok ? 4u : 0u);
            }
        }
        asm volatile("cp.async.commit_group;" ::: "memory");
        // advance incremental state
        #pragma unroll
        for (int kk = 0; kk < 4; kk++) {
            rst[kk] += 5;
            if (rst[kk] >= 9) { rst[kk] -= 9; coff[kk] += 4 * HW; }
            else coff[kk] += 3 * HW;
        }
    };

    // ---- prologue ----
    issueStage(0, 0);
    issueStage(1, 1);

    int sIdx = 0;
    for (int c0 = 0; c0 < NCHUNK; c0++) {
        if (c0 + 2 < NCHUNK) {
            issueStage(c0 + 2, (sIdx + 2) % NSTAGE);
            asm volatile("cp.async.wait_group 2;" ::: "memory");
        } else if (c0 + 2 == NCHUNK) {
            asm volatile("cp.async.wait_group 1;" ::: "memory");
        } else {
            asm volatile("cp.async.wait_group 0;" ::: "memory");
        }
        __syncthreads();

        const uint32_t stg = sbase + sIdx * STAGE;
        const uint32_t sA  = stg + aRowBase;
        const uint32_t sB  = stg + ATILE;

        #pragma unroll
        for (int t = 0; t < 2; t++) {
            uint32_t a0[4], a1[4];
            ldsm4(a0[0], a0[1], a0[2], a0[3],
                  sA + (((4u * t + 0 + aHi) ^ ls) << 4));
            ldsm4(a1[0], a1[1], a1[2], a1[3],
                  sA + (((4u * t + 2 + aHi) ^ ls) << 4));
            #pragma unroll
            for (int half = 0; half < 2; half++) {
                uint32_t bb[4][4];
                #pragma unroll
                for (int q = 0; q < 4; q++) {
                    int nb = half * 4 + q;
                    uint32_t rowB = (uint32_t)(nb * 8) * 128 + (uint32_t)(lane & 7) * 128;
                    ldsm4(bb[q][0], bb[q][1], bb[q][2], bb[q][3],
                          sB + rowB + (((4u * t + bHi) ^ ls) << 4));
                }
                #pragma unroll
                for (int q = 0; q < 4; q++)
                    mma_tf32(acc[half * 4 + q], a0, bb[q][0], bb[q][1]);
                #pragma unroll
                for (int q = 0; q < 4; q++)
                    mma_tf32(acc[half * 4 + q], a1, bb[q][2], bb[q][3]);
            }
        }
        __syncthreads();
        sIdx = (sIdx + 1) % NSTAGE;
    }

    // ---- epilogue ----
    {
        int r0 = o0 + wid * 16 + (lane >> 2);
        float bi0 = g_biasc[b * CH + r0];
        float bi1 = g_biasc[b * CH + r0 + 8];
        float* out0 = out + ((size_t)b * CH + r0) * HW;
        float* out1 = out0 + 8 * HW;
        #pragma unroll
        for (int nb = 0; nb < 8; nb++) {
            int p = p0 + nb * 8 + (lane & 3) * 2;
            *(float2*)(out0 + p) = make_float2(acc[nb][0] + bi0, acc[nb][1] + bi0);
            *(float2*)(out1 + p) = make_float2(acc[nb][2] + bi1, acc[nb][3] + bi1);
        }
    }
}

// ---------------------------------------------------------------------------
extern "C" void kernel_launch(void* const* d_in, const int* in_sizes, int n_in,
                              void* d_out, int out_size) {
    const float* x      = (const float*)d_in[0];
    const float* weight = (const float*)d_in[1];
    const float* bias   = (const float*)d_in[2];
    const float* gate_w = (const float*)d_in[3];
    const float* gate_b = (const float*)d_in[4];
    float* out = (float*)d_out;

    cudaFuncSetAttribute(conv_mma_kernel,
                         cudaFuncAttributeMaxDynamicSharedMemorySize, SMEM_BYTES);

    gap_kernel<<<BATCH * CH, 128>>>(x);
    gate_kernel<<<1, 256>>>(gate_w, gate_b, bias);
    combine_kernel<<<dim3(CH * KK2 / 4 / 256, BATCH), 256>>>(weight);
    xsplit_kernel<<<(int)((size_t)BATCH * CH * HW / 4 / 256), 256>>>(x);
    conv_mma_kernel<<<dim3(HW / BN, CH / BM, BATCH), 256, SMEM_BYTES>>>(out);
}